// round 15
// baseline (speedup 1.0000x reference)
#include <cuda_runtime.h>
#include <cstdint>

// ---------------- problem constants ----------------
#define TT 4096       // tokens (B*S)
#define DD 2048       // model dim
#define EE 8          // experts
#define FF 4096       // ffn dim

// ---------------- GEMM tile config -----------------
#define BM 128
#define BN 64
#define BK 32
#define NSTG 3             // pipeline stages
#define K8_UP (DD / 8)     // 256
#define K8_DN (FF / 8)     // 512
#define NT_UP (FF / BN)    // 64
#define NT_DN (DD / BN)    // 32

// smem: up = A(3*4096) + B1(3*2048) + B2(3*2048) floats = 98304 B -> 2 CTAs/SM
#define SMEM_UP   ((NSTG*4096 + 2*NSTG*2048) * 4)
// down = A(3*4096) + B(3*2048) floats = 73728 B -> 3 CTAs/SM
#define SMEM_DOWN ((NSTG*4096 + NSTG*2048) * 4)

// padded compact rows (each expert base aligned to 128)
#define HROWS (TT * 2 + EE * 128)                // 9216

// ---------------- device scratch --------------------
__device__ int   g_cnt[EE];
__device__ int   g_off[EE];
__device__ int   g_tok[EE * TT];
__device__ float g_wt [EE * TT];
__device__ float g_xf [(size_t)HROWS * DD];                // fragment-major gathered x (tf32)
__device__ float g_w1f[(size_t)EE * DD * FF];              // fragment-major W1
__device__ float g_w3f[(size_t)EE * DD * FF];              // fragment-major W3
__device__ float g_w2f[(size_t)EE * FF * DD];              // fragment-major W2
__device__ float g_hf [(size_t)HROWS * FF];                // fragment-major h

// ---------------- helpers ---------------------------
__device__ __forceinline__ void cp_async16(void* dst_smem, const void* src_glob) {
    uint32_t d = (uint32_t)__cvta_generic_to_shared(dst_smem);
    asm volatile("cp.async.cg.shared.global [%0], [%1], 16;\n" :: "r"(d), "l"(src_glob));
}
__device__ __forceinline__ void cp_commit() {
    asm volatile("cp.async.commit_group;\n" ::: "memory");
}
__device__ __forceinline__ void cp_wait1() {
    asm volatile("cp.async.wait_group 1;\n" ::: "memory");
}
__device__ __forceinline__ void cp_wait0() {
    asm volatile("cp.async.wait_group 0;\n" ::: "memory");
}
__device__ __forceinline__ uint32_t f2tf32(float f) {
    uint32_t r;
    asm("cvt.rna.tf32.f32 %0, %1;\n" : "=r"(r) : "f"(f));
    return r;
}
__device__ __forceinline__ void mma_tf32(float c[4], const uint32_t a[4], const uint32_t b[2]) {
    asm volatile(
        "mma.sync.aligned.m16n8k8.row.col.f32.tf32.tf32.f32 "
        "{%0,%1,%2,%3}, {%4,%5,%6,%7}, {%8,%9}, {%0,%1,%2,%3};\n"
        : "+f"(c[0]), "+f"(c[1]), "+f"(c[2]), "+f"(c[3])
        : "r"(a[0]), "r"(a[1]), "r"(a[2]), "r"(a[3]), "r"(b[0]), "r"(b[1]));
}

// ---------------- kernel: weight -> fragment-major + tf32 round -------
// Layout (per matrix): [e][nt][k8][wn(2)][half(2)][lane(32)][4]
//   x = W[k8*8+tg][nt*64 + wn*32 + half*16 + g]
//   y = W[k8*8+tg+4][same col]
//   z = W[k8*8+tg][col + 8]
//   w = W[k8*8+tg+4][col + 8]
// with g = lane>>2, tg = lane&3 -> m16n8k8 col-major B fragments.
__global__ void wfrag_kernel(const float* __restrict__ W, float4* __restrict__ out,
                             int NT, int K8, int ncols) {
    const int total = EE * NT * K8 * 2 * 2 * 32;   // float4 count
    int idx = blockIdx.x * blockDim.x + threadIdx.x;
    int stride = gridDim.x * blockDim.x;
    for (; idx < total; idx += stride) {
        int lane = idx & 31;
        int t1 = idx >> 5;
        int half = t1 & 1;
        int wn = (t1 >> 1) & 1;
        int t2 = t1 >> 2;
        int k8 = t2 % K8;
        int t3 = t2 / K8;
        int nt = t3 % NT;
        int e  = t3 / NT;

        int g = lane >> 2, tg = lane & 3;
        const float* We = W + (size_t)e * K8 * 8 * ncols;
        int row = k8 * 8 + tg;
        int col = nt * 64 + wn * 32 + half * 16 + g;

        float4 o;
        o.x = __uint_as_float(f2tf32(We[(size_t)row * ncols + col]));
        o.y = __uint_as_float(f2tf32(We[(size_t)(row + 4) * ncols + col]));
        o.z = __uint_as_float(f2tf32(We[(size_t)row * ncols + col + 8]));
        o.w = __uint_as_float(f2tf32(We[(size_t)(row + 4) * ncols + col + 8]));
        out[idx] = o;
    }
}

// ---------------- kernel: gather x -> fragment-major A (tf32) --------
// A fragment layout: [rg32][k8][mi(2)][lane(32)][4]
//   x = X[row0 + g][k8*8 + tg],     y = X[row0 + g + 8][k8*8 + tg]
//   z = X[row0 + g][k8*8 + tg + 4], w = X[row0 + g + 8][k8*8 + tg + 4]
// with row0 = rg*32 + mi*16 (local), g = lane>>2, tg = lane&3.
// grid (TT/BM, EE), 256 threads. Rows beyond cnt clamp to a valid token.
__global__ void gather_xf_kernel(const float* __restrict__ x) {
    const int e = blockIdx.y, mtile = blockIdx.x;
    const int cnt = g_cnt[e];
    if (mtile * BM >= cnt) return;

    __shared__ int stok[BM];
    const int tid = threadIdx.x;
    if (tid < BM) {
        int idx = mtile * BM + tid;
        stok[tid] = (idx < cnt) ? g_tok[e * TT + idx] : g_tok[e * TT];
    }
    __syncthreads();

    const int rg0 = (g_off[e] + mtile * BM) >> 5;   // first 32-row group (of 4)
    float4* out = (float4*)g_xf;

    for (int v = tid; v < BM * (DD / 4); v += 256) {   // 65536 float4
        int lane = v & 31;
        int t1 = v >> 5;
        int mi = t1 & 1;
        int t2 = t1 >> 1;
        int k8 = t2 & (K8_UP - 1);
        int rg = t2 >> 8;

        int g = lane >> 2, tg = lane & 3;
        int row0 = rg * 32 + mi * 16;
        const float* x1 = x + (size_t)stok[row0 + g] * DD;
        const float* x2 = x + (size_t)stok[row0 + g + 8] * DD;
        int c = k8 * 8 + tg;

        float4 o;
        o.x = __uint_as_float(f2tf32(x1[c]));
        o.y = __uint_as_float(f2tf32(x2[c]));
        o.z = __uint_as_float(f2tf32(x1[c + 4]));
        o.w = __uint_as_float(f2tf32(x2[c + 4]));
        out[(((size_t)(rg0 + rg) * K8_UP + k8) * 2 + mi) * 32 + lane] = o;
    }
}

// ---------------- kernel: zero y + counts ------------
__global__ void zero_kernel(float* __restrict__ y, size_t n) {
    size_t i = (size_t)blockIdx.x * blockDim.x + threadIdx.x;
    size_t stride = (size_t)gridDim.x * blockDim.x;
    for (; i < n; i += stride) y[i] = 0.0f;
    if (blockIdx.x == 0 && threadIdx.x < EE) g_cnt[threadIdx.x] = 0;
}

// ---------------- kernel: router ----------------------
__global__ void router_kernel(const float* __restrict__ x,
                              const float* __restrict__ Wg,
                              float* __restrict__ logits_out,
                              int write_logits) {
    const int warp = threadIdx.x >> 5;
    const int lane = threadIdx.x & 31;
    const int t = blockIdx.x * 8 + warp;
    if (t >= TT) return;

    float acc[EE];
#pragma unroll
    for (int e = 0; e < EE; ++e) acc[e] = 0.0f;
    const float* xr = x + (size_t)t * DD;
    for (int d = lane; d < DD; d += 32) {
        float xv = xr[d];
#pragma unroll
        for (int e = 0; e < EE; ++e) acc[e] += xv * Wg[e * DD + d];
    }
#pragma unroll
    for (int off = 16; off > 0; off >>= 1)
#pragma unroll
        for (int e = 0; e < EE; ++e) acc[e] += __shfl_down_sync(0xffffffffu, acc[e], off);

    if (lane == 0) {
        if (write_logits) {
#pragma unroll
            for (int e = 0; e < EE; ++e) logits_out[(size_t)t * EE + e] = acc[e];
        }
        int i1 = 0;
#pragma unroll
        for (int e = 1; e < EE; ++e) if (acc[e] > acc[i1]) i1 = e;
        int i2 = (i1 == 0) ? 1 : 0;
#pragma unroll
        for (int e = 0; e < EE; ++e) if (e != i1 && acc[e] > acc[i2]) i2 = e;
        float w1 = 1.0f / (1.0f + expf(acc[i2] - acc[i1]));
        float w2 = 1.0f - w1;
        int p1 = atomicAdd(&g_cnt[i1], 1);
        g_tok[i1 * TT + p1] = t; g_wt[i1 * TT + p1] = w1;
        int p2 = atomicAdd(&g_cnt[i2], 1);
        g_tok[i2 * TT + p2] = t; g_wt[i2 * TT + p2] = w2;
    }
}

// ---------------- kernel: prefix offsets (128-aligned) -----
__global__ void offsets_kernel() {
    if (threadIdx.x == 0 && blockIdx.x == 0) {
        int s = 0;
#pragma unroll
        for (int e = 0; e < EE; ++e) {
            g_off[e] = s;
            s += (g_cnt[e] + 127) & ~127;
        }
    }
}

// ---------------- kernel: up projection ---------------
// grid (mtile, ntile, e), 256 threads, 2 CTAs/SM
__global__ void __launch_bounds__(256, 2)
moe_up_kernel() {
    const int e     = blockIdx.z;
    const int mtile = blockIdx.x;   // fastest: concurrent CTAs share B in L2
    const int ntile = blockIdx.y;
    const int cnt   = g_cnt[e];
    if (mtile * BM >= cnt) return;

    extern __shared__ float sm[];
    float* As  = sm;                          // NSTG * 4096 (fragment-major A)
    float* B1s = sm + NSTG * 4096;            // NSTG * 2048
    float* B2s = B1s + NSTG * 2048;           // NSTG * 2048

    const int tid = threadIdx.x;
    const int hbase = g_off[e] + mtile * BM;  // 128-aligned
    const int rg0   = hbase >> 5;

    const float* W1e = g_w1f + ((size_t)(e * NT_UP + ntile) * K8_UP) * 512;
    const float* W3e = g_w3f + ((size_t)(e * NT_UP + ntile) * K8_UP) * 512;

    auto load_stage = [&](int ks, int buf) {
        float* Ab = As + buf * 4096;
#pragma unroll
        for (int v = tid; v < 1024; v += 256) {     // uint4 chunks
            int block = v >> 6, rem = v & 63;       // [rg][k8l] / [mi][lane]
            int rg = block >> 2, k8l = block & 3;
            const float* src = g_xf +
                (((size_t)(rg0 + rg) * K8_UP + ks * 4 + k8l) * 2) * 128 + rem * 4;
            cp_async16(Ab + v * 4, src);
        }
        float* B1b = B1s + buf * 2048;
        float* B2b = B2s + buf * 2048;
        const float* s1 = W1e + (size_t)(ks * 4) * 512;
        const float* s3 = W3e + (size_t)(ks * 4) * 512;
#pragma unroll
        for (int v = tid; v < 512; v += 256) {
            cp_async16(B1b + v * 4, s1 + v * 4);
            cp_async16(B2b + v * 4, s3 + v * 4);
        }
    };

    const int warp = tid >> 5;
    const int lane = tid & 31;
    const int rg  = warp & 3;         // 32-row group
    const int wnq = warp >> 2;        // 0/1
    const int g   = lane >> 2;
    const int tg  = lane & 3;

    float cg[2][4][4], cu[2][4][4];
#pragma unroll
    for (int mi = 0; mi < 2; ++mi)
#pragma unroll
        for (int ni = 0; ni < 4; ++ni)
#pragma unroll
            for (int j = 0; j < 4; ++j) { cg[mi][ni][j] = 0.f; cu[mi][ni][j] = 0.f; }

    load_stage(0, 0); cp_commit();
    load_stage(1, 1); cp_commit();

    const int KS = DD / BK;  // 64
    for (int ks = 0; ks < KS; ++ks) {
        if (ks + 1 < KS) cp_wait1(); else cp_wait0();
        __syncthreads();
        if (ks + 2 < KS) { load_stage(ks + 2, (ks + 2) % NSTG); cp_commit(); }

        const int cur = ks % NSTG;
        const uint4* Aq  = (const uint4*)(As  + cur * 4096);
        const uint4* B1q = (const uint4*)(B1s + cur * 2048);
        const uint4* B2q = (const uint4*)(B2s + cur * 2048);

#pragma unroll
        for (int k8 = 0; k8 < 4; ++k8) {
            uint32_t a[2][4];
#pragma unroll
            for (int mi = 0; mi < 2; ++mi) {
                uint4 qa = Aq[((rg * 4 + k8) * 2 + mi) * 32 + lane];
                a[mi][0] = qa.x; a[mi][1] = qa.y; a[mi][2] = qa.z; a[mi][3] = qa.w;
            }
            const int qb = k8 * 128 + wnq * 64 + lane;
            uint4 q10 = B1q[qb], q11 = B1q[qb + 32];
            uint4 q30 = B2q[qb], q31 = B2q[qb + 32];
            uint32_t b1[4][2], b2[4][2];
            b1[0][0] = q10.x; b1[0][1] = q10.y; b1[1][0] = q10.z; b1[1][1] = q10.w;
            b1[2][0] = q11.x; b1[2][1] = q11.y; b1[3][0] = q11.z; b1[3][1] = q11.w;
            b2[0][0] = q30.x; b2[0][1] = q30.y; b2[1][0] = q30.z; b2[1][1] = q30.w;
            b2[2][0] = q31.x; b2[2][1] = q31.y; b2[3][0] = q31.z; b2[3][1] = q31.w;
#pragma unroll
            for (int mi = 0; mi < 2; ++mi)
#pragma unroll
                for (int ni = 0; ni < 4; ++ni) {
                    mma_tf32(cg[mi][ni], a[mi], b1[ni]);
                    mma_tf32(cu[mi][ni], a[mi], b2[ni]);
                }
        }
    }

    // epilogue: silu(g)*u -> fragment-major g_hf (tf32-rounded)
    const int hb32  = hbase >> 5;
    const int mrem  = cnt - mtile * BM;
    const int wm    = rg * 32;
    const int nbase = ntile * BN + wnq * 32;
#pragma unroll
    for (int mi = 0; mi < 2; ++mi) {
#pragma unroll
        for (int ni = 0; ni < 4; ++ni) {
#pragma unroll
            for (int j = 0; j < 4; ++j) {
                int jh = j >> 1, jl = j & 1;
                int rl = wm + mi * 16 + g + 8 * jh;
                if (rl < mrem) {
                    int c0 = nbase + ni * 8 + tg * 2 + jl;
                    int rgG = hb32 + (rl >> 5);
                    int k8 = c0 >> 3;
                    int lane_d = g * 4 + (c0 & 3);
                    int elem = jh + 2 * ((c0 >> 2) & 1);
                    float gv = cg[mi][ni][j];
                    float uv = cu[mi][ni][j];
                    float s  = gv / (1.0f + __expf(-gv));
                    size_t off = (((size_t)rgG * K8_DN + k8) * 2 + mi) * 128 + lane_d * 4 + elem;
                    g_hf[off] = __uint_as_float(f2tf32(s * uv));
                }
            }
        }
    }
}

// ---------------- kernel: down projection -------------
// grid (mtile, ntile, e), 256 threads, 3 CTAs/SM
__global__ void __launch_bounds__(256, 3)
moe_down_kernel(float* __restrict__ y) {
    const int e     = blockIdx.z;
    const int mtile = blockIdx.x;
    const int ntile = blockIdx.y;
    const int cnt   = g_cnt[e];
    if (mtile * BM >= cnt) return;

    extern __shared__ float sm[];
    float* As = sm;                      // NSTG * 4096 (fragment-major A)
    float* Bs = sm + NSTG * 4096;        // NSTG * 2048
    __shared__ int   stok[BM];
    __shared__ float swt[BM];

    const int tid = threadIdx.x;
    if (tid < BM) {
        int idx = mtile * BM + tid;
        int ok = idx < cnt;
        stok[tid] = ok ? g_tok[e * TT + idx] : 0;
        swt[tid]  = ok ? g_wt[e * TT + idx] : 0.f;
    }
    __syncthreads();

    const int hbase = g_off[e] + mtile * BM;
    const int rg0   = hbase >> 5;
    const float* W2e = g_w2f + ((size_t)(e * NT_DN + ntile) * K8_DN) * 512;

    auto load_stage = [&](int ks, int buf) {
        float* Ab = As + buf * 4096;
#pragma unroll
        for (int v = tid; v < 1024; v += 256) {
            int block = v >> 6, rem = v & 63;
            int rg = block >> 2, k8l = block & 3;
            const float* src = g_hf +
                (((size_t)(rg0 + rg) * K8_DN + ks * 4 + k8l) * 2) * 128 + rem * 4;
            cp_async16(Ab + v * 4, src);
        }
        float* Bb = Bs + buf * 2048;
        const float* s2 = W2e + (size_t)(ks * 4) * 512;
#pragma unroll
        for (int v = tid; v < 512; v += 256) {
            cp_async16(Bb + v * 4, s2 + v * 4);
        }
    };

    const int warp = tid >> 5;
    const int lane = tid & 31;
    const int rg  = warp & 3;
    const int wnq = warp >> 2;
    const int g   = lane >> 2;
    const int tg  = lane & 3;

    float c[2][4][4];
#pragma unroll
    for (int mi = 0; mi < 2; ++mi)
#pragma unroll
        for (int ni = 0; ni < 4; ++ni)
#pragma unroll
            for (int j = 0; j < 4; ++j) c[mi][ni][j] = 0.f;

    load_stage(0, 0); cp_commit();
    load_stage(1, 1); cp_commit();

    const int KS = FF / BK;  // 128
    for (int ks = 0; ks < KS; ++ks) {
        if (ks + 1 < KS) cp_wait1(); else cp_wait0();
        __syncthreads();
        if (ks + 2 < KS) { load_stage(ks + 2, (ks + 2) % NSTG); cp_commit(); }

        const int cur = ks % NSTG;
        const uint4* Aq = (const uint4*)(As + cur * 4096);
        const uint4* Bq = (const uint4*)(Bs + cur * 2048);

#pragma unroll
        for (int k8 = 0; k8 < 4; ++k8) {
            uint32_t a[2][4];
#pragma unroll
            for (int mi = 0; mi < 2; ++mi) {
                uint4 qa = Aq[((rg * 4 + k8) * 2 + mi) * 32 + lane];
                a[mi][0] = qa.x; a[mi][1] = qa.y; a[mi][2] = qa.z; a[mi][3] = qa.w;
            }
            const int qb = k8 * 128 + wnq * 64 + lane;
            uint4 q0 = Bq[qb], q1 = Bq[qb + 32];
            uint32_t b[4][2];
            b[0][0] = q0.x; b[0][1] = q0.y; b[1][0] = q0.z; b[1][1] = q0.w;
            b[2][0] = q1.x; b[2][1] = q1.y; b[3][0] = q1.z; b[3][1] = q1.w;
#pragma unroll
            for (int mi = 0; mi < 2; ++mi)
#pragma unroll
                for (int ni = 0; ni < 4; ++ni)
                    mma_tf32(c[mi][ni], a[mi], b[ni]);
        }
    }

    // epilogue: weighted atomic scatter-add into y
    const int mrem = cnt - mtile * BM;
    const int wm = rg * 32;
    const int wn = wnq * 32;
#pragma unroll
    for (int mi = 0; mi < 2; ++mi) {
#pragma unroll
        for (int ni = 0; ni < 4; ++ni) {
            int r0 = wm + mi * 16 + g;
            int c0 = ntile * BN + wn + ni * 8 + tg * 2;
#pragma unroll
            for (int j = 0; j < 4; ++j) {
                int r = r0 + (j >> 1) * 8;
                int cc = c0 + (j & 1);
                if (r < mrem) {
                    atomicAdd(&y[(size_t)stok[r] * DD + cc], swt[r] * c[mi][ni][j]);
                }
            }
        }
    }
}

// ---------------- launch ------------------------------
extern "C" void kernel_launch(void* const* d_in, const int* in_sizes, int n_in,
                              void* d_out, int out_size) {
    const float* x  = (const float*)d_in[0];
    const float* Wg = (const float*)d_in[1];
    const float* W1 = (const float*)d_in[2];
    const float* W3 = (const float*)d_in[3];
    const float* W2 = (const float*)d_in[4];

    float* y = (float*)d_out;
    float* logits = nullptr;
    int write_logits = 0;
    if ((size_t)out_size >= (size_t)TT * DD + (size_t)TT * EE) {
        logits = y + (size_t)TT * DD;
        write_logits = 1;
    }

    cudaFuncSetAttribute(moe_up_kernel,
                         cudaFuncAttributeMaxDynamicSharedMemorySize, SMEM_UP);
    cudaFuncSetAttribute(moe_down_kernel,
                         cudaFuncAttributeMaxDynamicSharedMemorySize, SMEM_DOWN);

    float *w1f, *w3f, *w2f;
    cudaGetSymbolAddress((void**)&w1f, g_w1f);
    cudaGetSymbolAddress((void**)&w3f, g_w3f);
    cudaGetSymbolAddress((void**)&w2f, g_w2f);

    zero_kernel<<<4096, 256>>>(y, (size_t)TT * DD);
    wfrag_kernel<<<8192, 256>>>(W1, (float4*)w1f, NT_UP, K8_UP, FF);
    wfrag_kernel<<<8192, 256>>>(W3, (float4*)w3f, NT_UP, K8_UP, FF);
    wfrag_kernel<<<8192, 256>>>(W2, (float4*)w2f, NT_DN, K8_DN, DD);

    router_kernel<<<TT / 8, 256>>>(x, Wg, logits, write_logits);
    offsets_kernel<<<1, 32>>>();
    gather_xf_kernel<<<dim3(TT / BM, EE), 256>>>(x);
    moe_up_kernel<<<dim3(TT / BM, NT_UP, EE), 256, SMEM_UP>>>();
    moe_down_kernel<<<dim3(TT / BM, NT_DN, EE), 256, SMEM_DOWN>>>(y);
}

// round 16
// speedup vs baseline: 1.0029x; 1.0029x over previous
#include <cuda_runtime.h>
#include <cstdint>

// ---------------- problem constants ----------------
#define TT 4096       // tokens (B*S)
#define DD 2048       // model dim
#define EE 8          // experts
#define FF 4096       // ffn dim

// ---------------- GEMM tile config -----------------
#define BM 128
#define BN 64
#define BK 32
#define NSTG 3             // pipeline stages
#define K8_UP (DD / 8)     // 256
#define K8_DN (FF / 8)     // 512
#define NT_UP (FF / BN)    // 64
#define NT_DN (DD / BN)    // 32

// smem: up = A(3*4096) + B1(3*2048) + B2(3*2048) floats = 98304 B -> 2 CTAs/SM
#define SMEM_UP   ((NSTG*4096 + 2*NSTG*2048) * 4)
// down = A(3*4096) + B(3*2048) floats = 73728 B -> 3 CTAs/SM
#define SMEM_DOWN ((NSTG*4096 + NSTG*2048) * 4)

// padded compact rows (each expert base aligned to 128)
#define HROWS (TT * 2 + EE * 128)                // 9216

// ---------------- device scratch --------------------
__device__ int   g_cnt[EE];
__device__ int   g_off[EE];
__device__ int   g_tok[EE * TT];
__device__ float g_wt [EE * TT];
__device__ float g_xf [(size_t)HROWS * DD];                // fragment-major gathered x (tf32)
__device__ float g_w1f[(size_t)EE * DD * FF];              // fragment-major W1
__device__ float g_w3f[(size_t)EE * DD * FF];              // fragment-major W3
__device__ float g_w2f[(size_t)EE * FF * DD];              // fragment-major W2
__device__ float g_hf [(size_t)HROWS * FF];                // fragment-major h

// ---------------- helpers ---------------------------
__device__ __forceinline__ void cp_async16(void* dst_smem, const void* src_glob) {
    uint32_t d = (uint32_t)__cvta_generic_to_shared(dst_smem);
    asm volatile("cp.async.cg.shared.global [%0], [%1], 16;\n" :: "r"(d), "l"(src_glob));
}
__device__ __forceinline__ void cp_commit() {
    asm volatile("cp.async.commit_group;\n" ::: "memory");
}
__device__ __forceinline__ void cp_wait1() {
    asm volatile("cp.async.wait_group 1;\n" ::: "memory");
}
__device__ __forceinline__ void cp_wait0() {
    asm volatile("cp.async.wait_group 0;\n" ::: "memory");
}
__device__ __forceinline__ uint32_t f2tf32(float f) {
    uint32_t r;
    asm("cvt.rna.tf32.f32 %0, %1;\n" : "=r"(r) : "f"(f));
    return r;
}
__device__ __forceinline__ void mma_tf32(float c[4], const uint32_t a[4], const uint32_t b[2]) {
    asm volatile(
        "mma.sync.aligned.m16n8k8.row.col.f32.tf32.tf32.f32 "
        "{%0,%1,%2,%3}, {%4,%5,%6,%7}, {%8,%9}, {%0,%1,%2,%3};\n"
        : "+f"(c[0]), "+f"(c[1]), "+f"(c[2]), "+f"(c[3])
        : "r"(a[0]), "r"(a[1]), "r"(a[2]), "r"(a[3]), "r"(b[0]), "r"(b[1]));
}

// ---------------- kernel: weight -> fragment-major + tf32 round -------
// Layout (per matrix): [e][nt][k8][wn(2)][half(2)][lane(32)][4]
//   x = W[k8*8+tg][nt*64 + wn*32 + half*16 + g]
//   y = W[k8*8+tg+4][same col]
//   z = W[k8*8+tg][col + 8]
//   w = W[k8*8+tg+4][col + 8]
// with g = lane>>2, tg = lane&3 -> m16n8k8 col-major B fragments.
__global__ void wfrag_kernel(const float* __restrict__ W, float4* __restrict__ out,
                             int NT, int K8, int ncols) {
    const int total = EE * NT * K8 * 2 * 2 * 32;   // float4 count
    int idx = blockIdx.x * blockDim.x + threadIdx.x;
    int stride = gridDim.x * blockDim.x;
    for (; idx < total; idx += stride) {
        int lane = idx & 31;
        int t1 = idx >> 5;
        int half = t1 & 1;
        int wn = (t1 >> 1) & 1;
        int t2 = t1 >> 2;
        int k8 = t2 % K8;
        int t3 = t2 / K8;
        int nt = t3 % NT;
        int e  = t3 / NT;

        int g = lane >> 2, tg = lane & 3;
        const float* We = W + (size_t)e * K8 * 8 * ncols;
        int row = k8 * 8 + tg;
        int col = nt * 64 + wn * 32 + half * 16 + g;

        float4 o;
        o.x = __uint_as_float(f2tf32(We[(size_t)row * ncols + col]));
        o.y = __uint_as_float(f2tf32(We[(size_t)(row + 4) * ncols + col]));
        o.z = __uint_as_float(f2tf32(We[(size_t)row * ncols + col + 8]));
        o.w = __uint_as_float(f2tf32(We[(size_t)(row + 4) * ncols + col + 8]));
        out[idx] = o;
    }
}

// ---------------- kernel: gather x -> fragment-major A (tf32) --------
// A fragment layout: [rg32][k8][mi(2)][lane(32)][4]
//   x = X[row0 + g][k8*8 + tg],     y = X[row0 + g + 8][k8*8 + tg]
//   z = X[row0 + g][k8*8 + tg + 4], w = X[row0 + g + 8][k8*8 + tg + 4]
// with row0 = rg*32 + mi*16 (local), g = lane>>2, tg = lane&3.
// grid (TT/BM, EE), 256 threads. Rows beyond cnt clamp to a valid token.
__global__ void gather_xf_kernel(const float* __restrict__ x) {
    const int e = blockIdx.y, mtile = blockIdx.x;
    const int cnt = g_cnt[e];
    if (mtile * BM >= cnt) return;

    __shared__ int stok[BM];
    const int tid = threadIdx.x;
    if (tid < BM) {
        int idx = mtile * BM + tid;
        stok[tid] = (idx < cnt) ? g_tok[e * TT + idx] : g_tok[e * TT];
    }
    __syncthreads();

    const int rg0 = (g_off[e] + mtile * BM) >> 5;   // first 32-row group (of 4)
    float4* out = (float4*)g_xf;

    for (int v = tid; v < BM * (DD / 4); v += 256) {   // 65536 float4
        int lane = v & 31;
        int t1 = v >> 5;
        int mi = t1 & 1;
        int t2 = t1 >> 1;
        int k8 = t2 & (K8_UP - 1);
        int rg = t2 >> 8;

        int g = lane >> 2, tg = lane & 3;
        int row0 = rg * 32 + mi * 16;
        const float* x1 = x + (size_t)stok[row0 + g] * DD;
        const float* x2 = x + (size_t)stok[row0 + g + 8] * DD;
        int c = k8 * 8 + tg;

        float4 o;
        o.x = __uint_as_float(f2tf32(x1[c]));
        o.y = __uint_as_float(f2tf32(x2[c]));
        o.z = __uint_as_float(f2tf32(x1[c + 4]));
        o.w = __uint_as_float(f2tf32(x2[c + 4]));
        out[(((size_t)(rg0 + rg) * K8_UP + k8) * 2 + mi) * 32 + lane] = o;
    }
}

// ---------------- kernel: zero y + counts ------------
__global__ void zero_kernel(float* __restrict__ y, size_t n) {
    size_t i = (size_t)blockIdx.x * blockDim.x + threadIdx.x;
    size_t stride = (size_t)gridDim.x * blockDim.x;
    for (; i < n; i += stride) y[i] = 0.0f;
    if (blockIdx.x == 0 && threadIdx.x < EE) g_cnt[threadIdx.x] = 0;
}

// ---------------- kernel: router ----------------------
__global__ void router_kernel(const float* __restrict__ x,
                              const float* __restrict__ Wg,
                              float* __restrict__ logits_out,
                              int write_logits) {
    const int warp = threadIdx.x >> 5;
    const int lane = threadIdx.x & 31;
    const int t = blockIdx.x * 8 + warp;
    if (t >= TT) return;

    float acc[EE];
#pragma unroll
    for (int e = 0; e < EE; ++e) acc[e] = 0.0f;
    const float* xr = x + (size_t)t * DD;
    for (int d = lane; d < DD; d += 32) {
        float xv = xr[d];
#pragma unroll
        for (int e = 0; e < EE; ++e) acc[e] += xv * Wg[e * DD + d];
    }
#pragma unroll
    for (int off = 16; off > 0; off >>= 1)
#pragma unroll
        for (int e = 0; e < EE; ++e) acc[e] += __shfl_down_sync(0xffffffffu, acc[e], off);

    if (lane == 0) {
        if (write_logits) {
#pragma unroll
            for (int e = 0; e < EE; ++e) logits_out[(size_t)t * EE + e] = acc[e];
        }
        int i1 = 0;
#pragma unroll
        for (int e = 1; e < EE; ++e) if (acc[e] > acc[i1]) i1 = e;
        int i2 = (i1 == 0) ? 1 : 0;
#pragma unroll
        for (int e = 0; e < EE; ++e) if (e != i1 && acc[e] > acc[i2]) i2 = e;
        float w1 = 1.0f / (1.0f + expf(acc[i2] - acc[i1]));
        float w2 = 1.0f - w1;
        int p1 = atomicAdd(&g_cnt[i1], 1);
        g_tok[i1 * TT + p1] = t; g_wt[i1 * TT + p1] = w1;
        int p2 = atomicAdd(&g_cnt[i2], 1);
        g_tok[i2 * TT + p2] = t; g_wt[i2 * TT + p2] = w2;
    }
}

// ---------------- kernel: prefix offsets (128-aligned) -----
__global__ void offsets_kernel() {
    if (threadIdx.x == 0 && blockIdx.x == 0) {
        int s = 0;
#pragma unroll
        for (int e = 0; e < EE; ++e) {
            g_off[e] = s;
            s += (g_cnt[e] + 127) & ~127;
        }
    }
}

// ---------------- kernel: up projection ---------------
// grid (mtile, ntile, e), 256 threads, 2 CTAs/SM
__global__ void __launch_bounds__(256, 2)
moe_up_kernel() {
    const int e     = blockIdx.z;
    const int mtile = blockIdx.x;   // fastest: concurrent CTAs share B in L2
    const int ntile = blockIdx.y;
    const int cnt   = g_cnt[e];
    if (mtile * BM >= cnt) return;

    extern __shared__ float sm[];
    float* As  = sm;                          // NSTG * 4096 (fragment-major A)
    float* B1s = sm + NSTG * 4096;            // NSTG * 2048
    float* B2s = B1s + NSTG * 2048;           // NSTG * 2048

    const int tid = threadIdx.x;
    const int hbase = g_off[e] + mtile * BM;  // 128-aligned
    const int rg0   = hbase >> 5;

    const float* W1e = g_w1f + ((size_t)(e * NT_UP + ntile) * K8_UP) * 512;
    const float* W3e = g_w3f + ((size_t)(e * NT_UP + ntile) * K8_UP) * 512;

    auto load_stage = [&](int ks, int buf) {
        float* Ab = As + buf * 4096;
#pragma unroll
        for (int v = tid; v < 1024; v += 256) {     // uint4 chunks
            int block = v >> 6, rem = v & 63;       // [rg][k8l] / [mi][lane]
            int rg = block >> 2, k8l = block & 3;
            const float* src = g_xf +
                (((size_t)(rg0 + rg) * K8_UP + ks * 4 + k8l) * 2) * 128 + rem * 4;
            cp_async16(Ab + v * 4, src);
        }
        float* B1b = B1s + buf * 2048;
        float* B2b = B2s + buf * 2048;
        const float* s1 = W1e + (size_t)(ks * 4) * 512;
        const float* s3 = W3e + (size_t)(ks * 4) * 512;
#pragma unroll
        for (int v = tid; v < 512; v += 256) {
            cp_async16(B1b + v * 4, s1 + v * 4);
            cp_async16(B2b + v * 4, s3 + v * 4);
        }
    };

    const int warp = tid >> 5;
    const int lane = tid & 31;
    const int rg  = warp & 3;         // 32-row group
    const int wnq = warp >> 2;        // 0/1
    const int g   = lane >> 2;
    const int tg  = lane & 3;

    float cg[2][4][4], cu[2][4][4];
#pragma unroll
    for (int mi = 0; mi < 2; ++mi)
#pragma unroll
        for (int ni = 0; ni < 4; ++ni)
#pragma unroll
            for (int j = 0; j < 4; ++j) { cg[mi][ni][j] = 0.f; cu[mi][ni][j] = 0.f; }

    load_stage(0, 0); cp_commit();
    load_stage(1, 1); cp_commit();

    const int KS = DD / BK;  // 64
    for (int ks = 0; ks < KS; ++ks) {
        if (ks + 1 < KS) cp_wait1(); else cp_wait0();
        __syncthreads();
        if (ks + 2 < KS) { load_stage(ks + 2, (ks + 2) % NSTG); cp_commit(); }

        const int cur = ks % NSTG;
        const uint4* Aq  = (const uint4*)(As  + cur * 4096);
        const uint4* B1q = (const uint4*)(B1s + cur * 2048);
        const uint4* B2q = (const uint4*)(B2s + cur * 2048);

#pragma unroll
        for (int k8 = 0; k8 < 4; ++k8) {
            uint32_t a[2][4];
#pragma unroll
            for (int mi = 0; mi < 2; ++mi) {
                uint4 qa = Aq[((rg * 4 + k8) * 2 + mi) * 32 + lane];
                a[mi][0] = qa.x; a[mi][1] = qa.y; a[mi][2] = qa.z; a[mi][3] = qa.w;
            }
            const int qb = k8 * 128 + wnq * 64 + lane;
            uint4 q10 = B1q[qb], q11 = B1q[qb + 32];
            uint4 q30 = B2q[qb], q31 = B2q[qb + 32];
            uint32_t b1[4][2], b2[4][2];
            b1[0][0] = q10.x; b1[0][1] = q10.y; b1[1][0] = q10.z; b1[1][1] = q10.w;
            b1[2][0] = q11.x; b1[2][1] = q11.y; b1[3][0] = q11.z; b1[3][1] = q11.w;
            b2[0][0] = q30.x; b2[0][1] = q30.y; b2[1][0] = q30.z; b2[1][1] = q30.w;
            b2[2][0] = q31.x; b2[2][1] = q31.y; b2[3][0] = q31.z; b2[3][1] = q31.w;
#pragma unroll
            for (int mi = 0; mi < 2; ++mi)
#pragma unroll
                for (int ni = 0; ni < 4; ++ni) {
                    mma_tf32(cg[mi][ni], a[mi], b1[ni]);
                    mma_tf32(cu[mi][ni], a[mi], b2[ni]);
                }
        }
    }

    // epilogue: silu(g)*u -> fragment-major g_hf (tf32-rounded)
    const int hb32  = hbase >> 5;
    const int mrem  = cnt - mtile * BM;
    const int wm    = rg * 32;
    const int nbase = ntile * BN + wnq * 32;
#pragma unroll
    for (int mi = 0; mi < 2; ++mi) {
#pragma unroll
        for (int ni = 0; ni < 4; ++ni) {
#pragma unroll
            for (int j = 0; j < 4; ++j) {
                int jh = j >> 1, jl = j & 1;
                int rl = wm + mi * 16 + g + 8 * jh;
                if (rl < mrem) {
                    int c0 = nbase + ni * 8 + tg * 2 + jl;
                    int rgG = hb32 + (rl >> 5);
                    int k8 = c0 >> 3;
                    int lane_d = g * 4 + (c0 & 3);
                    int elem = jh + 2 * ((c0 >> 2) & 1);
                    float gv = cg[mi][ni][j];
                    float uv = cu[mi][ni][j];
                    float s  = gv / (1.0f + __expf(-gv));
                    size_t off = (((size_t)rgG * K8_DN + k8) * 2 + mi) * 128 + lane_d * 4 + elem;
                    g_hf[off] = __uint_as_float(f2tf32(s * uv));
                }
            }
        }
    }
}

// ---------------- kernel: down projection -------------
// grid (mtile, ntile, e), 256 threads, 3 CTAs/SM
__global__ void __launch_bounds__(256, 3)
moe_down_kernel(float* __restrict__ y) {
    const int e     = blockIdx.z;
    const int mtile = blockIdx.x;
    const int ntile = blockIdx.y;
    const int cnt   = g_cnt[e];
    if (mtile * BM >= cnt) return;

    extern __shared__ float sm[];
    float* As = sm;                      // NSTG * 4096 (fragment-major A)
    float* Bs = sm + NSTG * 4096;        // NSTG * 2048
    __shared__ int   stok[BM];
    __shared__ float swt[BM];

    const int tid = threadIdx.x;
    if (tid < BM) {
        int idx = mtile * BM + tid;
        int ok = idx < cnt;
        stok[tid] = ok ? g_tok[e * TT + idx] : 0;
        swt[tid]  = ok ? g_wt[e * TT + idx] : 0.f;
    }
    __syncthreads();

    const int hbase = g_off[e] + mtile * BM;
    const int rg0   = hbase >> 5;
    const float* W2e = g_w2f + ((size_t)(e * NT_DN + ntile) * K8_DN) * 512;

    auto load_stage = [&](int ks, int buf) {
        float* Ab = As + buf * 4096;
#pragma unroll
        for (int v = tid; v < 1024; v += 256) {
            int block = v >> 6, rem = v & 63;
            int rg = block >> 2, k8l = block & 3;
            const float* src = g_hf +
                (((size_t)(rg0 + rg) * K8_DN + ks * 4 + k8l) * 2) * 128 + rem * 4;
            cp_async16(Ab + v * 4, src);
        }
        float* Bb = Bs + buf * 2048;
        const float* s2 = W2e + (size_t)(ks * 4) * 512;
#pragma unroll
        for (int v = tid; v < 512; v += 256) {
            cp_async16(Bb + v * 4, s2 + v * 4);
        }
    };

    const int warp = tid >> 5;
    const int lane = tid & 31;
    const int rg  = warp & 3;
    const int wnq = warp >> 2;
    const int g   = lane >> 2;
    const int tg  = lane & 3;

    float c[2][4][4];
#pragma unroll
    for (int mi = 0; mi < 2; ++mi)
#pragma unroll
        for (int ni = 0; ni < 4; ++ni)
#pragma unroll
            for (int j = 0; j < 4; ++j) c[mi][ni][j] = 0.f;

    load_stage(0, 0); cp_commit();
    load_stage(1, 1); cp_commit();

    const int KS = FF / BK;  // 128
    for (int ks = 0; ks < KS; ++ks) {
        if (ks + 1 < KS) cp_wait1(); else cp_wait0();
        __syncthreads();
        if (ks + 2 < KS) { load_stage(ks + 2, (ks + 2) % NSTG); cp_commit(); }

        const int cur = ks % NSTG;
        const uint4* Aq = (const uint4*)(As + cur * 4096);
        const uint4* Bq = (const uint4*)(Bs + cur * 2048);

#pragma unroll
        for (int k8 = 0; k8 < 4; ++k8) {
            uint32_t a[2][4];
#pragma unroll
            for (int mi = 0; mi < 2; ++mi) {
                uint4 qa = Aq[((rg * 4 + k8) * 2 + mi) * 32 + lane];
                a[mi][0] = qa.x; a[mi][1] = qa.y; a[mi][2] = qa.z; a[mi][3] = qa.w;
            }
            const int qb = k8 * 128 + wnq * 64 + lane;
            uint4 q0 = Bq[qb], q1 = Bq[qb + 32];
            uint32_t b[4][2];
            b[0][0] = q0.x; b[0][1] = q0.y; b[1][0] = q0.z; b[1][1] = q0.w;
            b[2][0] = q1.x; b[2][1] = q1.y; b[3][0] = q1.z; b[3][1] = q1.w;
#pragma unroll
            for (int mi = 0; mi < 2; ++mi)
#pragma unroll
                for (int ni = 0; ni < 4; ++ni)
                    mma_tf32(c[mi][ni], a[mi], b[ni]);
        }
    }

    // epilogue: weighted atomic scatter-add into y
    const int mrem = cnt - mtile * BM;
    const int wm = rg * 32;
    const int wn = wnq * 32;
#pragma unroll
    for (int mi = 0; mi < 2; ++mi) {
#pragma unroll
        for (int ni = 0; ni < 4; ++ni) {
            int r0 = wm + mi * 16 + g;
            int c0 = ntile * BN + wn + ni * 8 + tg * 2;
#pragma unroll
            for (int j = 0; j < 4; ++j) {
                int r = r0 + (j >> 1) * 8;
                int cc = c0 + (j & 1);
                if (r < mrem) {
                    atomicAdd(&y[(size_t)stok[r] * DD + cc], swt[r] * c[mi][ni][j]);
                }
            }
        }
    }
}

// ---------------- launch ------------------------------
extern "C" void kernel_launch(void* const* d_in, const int* in_sizes, int n_in,
                              void* d_out, int out_size) {
    const float* x  = (const float*)d_in[0];
    const float* Wg = (const float*)d_in[1];
    const float* W1 = (const float*)d_in[2];
    const float* W3 = (const float*)d_in[3];
    const float* W2 = (const float*)d_in[4];

    float* y = (float*)d_out;
    float* logits = nullptr;
    int write_logits = 0;
    if ((size_t)out_size >= (size_t)TT * DD + (size_t)TT * EE) {
        logits = y + (size_t)TT * DD;
        write_logits = 1;
    }

    cudaFuncSetAttribute(moe_up_kernel,
                         cudaFuncAttributeMaxDynamicSharedMemorySize, SMEM_UP);
    cudaFuncSetAttribute(moe_down_kernel,
                         cudaFuncAttributeMaxDynamicSharedMemorySize, SMEM_DOWN);

    float *w1f, *w3f, *w2f;
    cudaGetSymbolAddress((void**)&w1f, g_w1f);
    cudaGetSymbolAddress((void**)&w3f, g_w3f);
    cudaGetSymbolAddress((void**)&w2f, g_w2f);

    zero_kernel<<<4096, 256>>>(y, (size_t)TT * DD);
    wfrag_kernel<<<8192, 256>>>(W1, (float4*)w1f, NT_UP, K8_UP, FF);
    wfrag_kernel<<<8192, 256>>>(W3, (float4*)w3f, NT_UP, K8_UP, FF);
    wfrag_kernel<<<8192, 256>>>(W2, (float4*)w2f, NT_DN, K8_DN, DD);

    router_kernel<<<TT / 8, 256>>>(x, Wg, logits, write_logits);
    offsets_kernel<<<1, 32>>>();
    gather_xf_kernel<<<dim3(TT / BM, EE), 256>>>(x);
    moe_up_kernel<<<dim3(TT / BM, NT_UP, EE), 256, SMEM_UP>>>();
    moe_down_kernel<<<dim3(TT / BM, NT_DN, EE), 256, SMEM_DOWN>>>(y);
}

// round 17
// speedup vs baseline: 1.0032x; 1.0003x over previous
#include <cuda_runtime.h>
#include <cstdint>

// ---------------- problem constants ----------------
#define TT 4096       // tokens (B*S)
#define DD 2048       // model dim
#define EE 8          // experts
#define FF 4096       // ffn dim

// ---------------- GEMM tile config -----------------
#define BM 128
#define BN 64
#define BK 32
#define NSTG 3             // pipeline stages
#define K8_UP (DD / 8)     // 256
#define K8_DN (FF / 8)     // 512
#define NT_UP (FF / BN)    // 64
#define NT_DN (DD / BN)    // 32

// smem: up = A(3*4096) + B1(3*2048) + B2(3*2048) floats = 98304 B -> 2 CTAs/SM
#define SMEM_UP   ((NSTG*4096 + 2*NSTG*2048) * 4)
// down = A(3*4096) + B(3*2048) floats = 73728 B -> 3 CTAs/SM
#define SMEM_DOWN ((NSTG*4096 + NSTG*2048) * 4)

// padded compact rows (each expert base aligned to 128)
#define HROWS (TT * 2 + EE * 128)                // 9216

// ---------------- device scratch --------------------
__device__ int   g_cnt[EE];
__device__ int   g_off[EE];
__device__ int   g_tok[EE * TT];
__device__ float g_wt [EE * TT];
__device__ float g_xf [(size_t)HROWS * DD];                // fragment-major gathered x (tf32)
__device__ float g_w1f[(size_t)EE * DD * FF];              // fragment-major W1
__device__ float g_w3f[(size_t)EE * DD * FF];              // fragment-major W3
__device__ float g_w2f[(size_t)EE * FF * DD];              // fragment-major W2
__device__ float g_hf [(size_t)HROWS * FF];                // fragment-major h

// ---------------- helpers ---------------------------
__device__ __forceinline__ void cp_async16(void* dst_smem, const void* src_glob) {
    uint32_t d = (uint32_t)__cvta_generic_to_shared(dst_smem);
    asm volatile("cp.async.cg.shared.global [%0], [%1], 16;\n" :: "r"(d), "l"(src_glob));
}
__device__ __forceinline__ void cp_commit() {
    asm volatile("cp.async.commit_group;\n" ::: "memory");
}
__device__ __forceinline__ void cp_wait1() {
    asm volatile("cp.async.wait_group 1;\n" ::: "memory");
}
__device__ __forceinline__ void cp_wait0() {
    asm volatile("cp.async.wait_group 0;\n" ::: "memory");
}
__device__ __forceinline__ uint32_t f2tf32(float f) {
    uint32_t r;
    asm("cvt.rna.tf32.f32 %0, %1;\n" : "=r"(r) : "f"(f));
    return r;
}
__device__ __forceinline__ void mma_tf32(float c[4], const uint32_t a[4], const uint32_t b[2]) {
    asm volatile(
        "mma.sync.aligned.m16n8k8.row.col.f32.tf32.tf32.f32 "
        "{%0,%1,%2,%3}, {%4,%5,%6,%7}, {%8,%9}, {%0,%1,%2,%3};\n"
        : "+f"(c[0]), "+f"(c[1]), "+f"(c[2]), "+f"(c[3])
        : "r"(a[0]), "r"(a[1]), "r"(a[2]), "r"(a[3]), "r"(b[0]), "r"(b[1]));
}

// ---------------- kernel: weight -> fragment-major + tf32 round -------
// Layout (per matrix): [e][nt][k8][wn(2)][half(2)][lane(32)][4]
//   x = W[k8*8+tg][nt*64 + wn*32 + half*16 + g]
//   y = W[k8*8+tg+4][same col]
//   z = W[k8*8+tg][col + 8]
//   w = W[k8*8+tg+4][col + 8]
// with g = lane>>2, tg = lane&3 -> m16n8k8 col-major B fragments.
__global__ void wfrag_kernel(const float* __restrict__ W, float4* __restrict__ out,
                             int NT, int K8, int ncols) {
    const int total = EE * NT * K8 * 2 * 2 * 32;   // float4 count
    int idx = blockIdx.x * blockDim.x + threadIdx.x;
    int stride = gridDim.x * blockDim.x;
    for (; idx < total; idx += stride) {
        int lane = idx & 31;
        int t1 = idx >> 5;
        int half = t1 & 1;
        int wn = (t1 >> 1) & 1;
        int t2 = t1 >> 2;
        int k8 = t2 % K8;
        int t3 = t2 / K8;
        int nt = t3 % NT;
        int e  = t3 / NT;

        int g = lane >> 2, tg = lane & 3;
        const float* We = W + (size_t)e * K8 * 8 * ncols;
        int row = k8 * 8 + tg;
        int col = nt * 64 + wn * 32 + half * 16 + g;

        float4 o;
        o.x = __uint_as_float(f2tf32(We[(size_t)row * ncols + col]));
        o.y = __uint_as_float(f2tf32(We[(size_t)(row + 4) * ncols + col]));
        o.z = __uint_as_float(f2tf32(We[(size_t)row * ncols + col + 8]));
        o.w = __uint_as_float(f2tf32(We[(size_t)(row + 4) * ncols + col + 8]));
        out[idx] = o;
    }
}

// ---------------- kernel: gather x -> fragment-major A (tf32) --------
// A fragment layout: [rg32][k8][mi(2)][lane(32)][4]
//   x = X[row0 + g][k8*8 + tg],     y = X[row0 + g + 8][k8*8 + tg]
//   z = X[row0 + g][k8*8 + tg + 4], w = X[row0 + g + 8][k8*8 + tg + 4]
// with row0 = rg*32 + mi*16 (local), g = lane>>2, tg = lane&3.
// grid (TT/BM, EE), 256 threads. Rows beyond cnt clamp to a valid token.
__global__ void gather_xf_kernel(const float* __restrict__ x) {
    const int e = blockIdx.y, mtile = blockIdx.x;
    const int cnt = g_cnt[e];
    if (mtile * BM >= cnt) return;

    __shared__ int stok[BM];
    const int tid = threadIdx.x;
    if (tid < BM) {
        int idx = mtile * BM + tid;
        stok[tid] = (idx < cnt) ? g_tok[e * TT + idx] : g_tok[e * TT];
    }
    __syncthreads();

    const int rg0 = (g_off[e] + mtile * BM) >> 5;   // first 32-row group (of 4)
    float4* out = (float4*)g_xf;

    for (int v = tid; v < BM * (DD / 4); v += 256) {   // 65536 float4
        int lane = v & 31;
        int t1 = v >> 5;
        int mi = t1 & 1;
        int t2 = t1 >> 1;
        int k8 = t2 & (K8_UP - 1);
        int rg = t2 >> 8;

        int g = lane >> 2, tg = lane & 3;
        int row0 = rg * 32 + mi * 16;
        const float* x1 = x + (size_t)stok[row0 + g] * DD;
        const float* x2 = x + (size_t)stok[row0 + g + 8] * DD;
        int c = k8 * 8 + tg;

        float4 o;
        o.x = __uint_as_float(f2tf32(x1[c]));
        o.y = __uint_as_float(f2tf32(x2[c]));
        o.z = __uint_as_float(f2tf32(x1[c + 4]));
        o.w = __uint_as_float(f2tf32(x2[c + 4]));
        out[(((size_t)(rg0 + rg) * K8_UP + k8) * 2 + mi) * 32 + lane] = o;
    }
}

// ---------------- kernel: zero y + counts ------------
__global__ void zero_kernel(float* __restrict__ y, size_t n) {
    size_t i = (size_t)blockIdx.x * blockDim.x + threadIdx.x;
    size_t stride = (size_t)gridDim.x * blockDim.x;
    for (; i < n; i += stride) y[i] = 0.0f;
    if (blockIdx.x == 0 && threadIdx.x < EE) g_cnt[threadIdx.x] = 0;
}

// ---------------- kernel: router ----------------------
__global__ void router_kernel(const float* __restrict__ x,
                              const float* __restrict__ Wg,
                              float* __restrict__ logits_out,
                              int write_logits) {
    const int warp = threadIdx.x >> 5;
    const int lane = threadIdx.x & 31;
    const int t = blockIdx.x * 8 + warp;
    if (t >= TT) return;

    float acc[EE];
#pragma unroll
    for (int e = 0; e < EE; ++e) acc[e] = 0.0f;
    const float* xr = x + (size_t)t * DD;
    for (int d = lane; d < DD; d += 32) {
        float xv = xr[d];
#pragma unroll
        for (int e = 0; e < EE; ++e) acc[e] += xv * Wg[e * DD + d];
    }
#pragma unroll
    for (int off = 16; off > 0; off >>= 1)
#pragma unroll
        for (int e = 0; e < EE; ++e) acc[e] += __shfl_down_sync(0xffffffffu, acc[e], off);

    if (lane == 0) {
        if (write_logits) {
#pragma unroll
            for (int e = 0; e < EE; ++e) logits_out[(size_t)t * EE + e] = acc[e];
        }
        int i1 = 0;
#pragma unroll
        for (int e = 1; e < EE; ++e) if (acc[e] > acc[i1]) i1 = e;
        int i2 = (i1 == 0) ? 1 : 0;
#pragma unroll
        for (int e = 0; e < EE; ++e) if (e != i1 && acc[e] > acc[i2]) i2 = e;
        float w1 = 1.0f / (1.0f + expf(acc[i2] - acc[i1]));
        float w2 = 1.0f - w1;
        int p1 = atomicAdd(&g_cnt[i1], 1);
        g_tok[i1 * TT + p1] = t; g_wt[i1 * TT + p1] = w1;
        int p2 = atomicAdd(&g_cnt[i2], 1);
        g_tok[i2 * TT + p2] = t; g_wt[i2 * TT + p2] = w2;
    }
}

// ---------------- kernel: prefix offsets (128-aligned) -----
__global__ void offsets_kernel() {
    if (threadIdx.x == 0 && blockIdx.x == 0) {
        int s = 0;
#pragma unroll
        for (int e = 0; e < EE; ++e) {
            g_off[e] = s;
            s += (g_cnt[e] + 127) & ~127;
        }
    }
}

// ---------------- kernel: up projection ---------------
// grid (mtile, ntile, e), 256 threads, 2 CTAs/SM
__global__ void __launch_bounds__(256, 2)
moe_up_kernel() {
    const int e     = blockIdx.z;
    const int mtile = blockIdx.x;   // fastest: concurrent CTAs share B in L2
    const int ntile = blockIdx.y;
    const int cnt   = g_cnt[e];
    if (mtile * BM >= cnt) return;

    extern __shared__ float sm[];
    float* As  = sm;                          // NSTG * 4096 (fragment-major A)
    float* B1s = sm + NSTG * 4096;            // NSTG * 2048
    float* B2s = B1s + NSTG * 2048;           // NSTG * 2048

    const int tid = threadIdx.x;
    const int hbase = g_off[e] + mtile * BM;  // 128-aligned
    const int rg0   = hbase >> 5;

    const float* W1e = g_w1f + ((size_t)(e * NT_UP + ntile) * K8_UP) * 512;
    const float* W3e = g_w3f + ((size_t)(e * NT_UP + ntile) * K8_UP) * 512;

    auto load_stage = [&](int ks, int buf) {
        float* Ab = As + buf * 4096;
#pragma unroll
        for (int v = tid; v < 1024; v += 256) {     // uint4 chunks
            int block = v >> 6, rem = v & 63;       // [rg][k8l] / [mi][lane]
            int rg = block >> 2, k8l = block & 3;
            const float* src = g_xf +
                (((size_t)(rg0 + rg) * K8_UP + ks * 4 + k8l) * 2) * 128 + rem * 4;
            cp_async16(Ab + v * 4, src);
        }
        float* B1b = B1s + buf * 2048;
        float* B2b = B2s + buf * 2048;
        const float* s1 = W1e + (size_t)(ks * 4) * 512;
        const float* s3 = W3e + (size_t)(ks * 4) * 512;
#pragma unroll
        for (int v = tid; v < 512; v += 256) {
            cp_async16(B1b + v * 4, s1 + v * 4);
            cp_async16(B2b + v * 4, s3 + v * 4);
        }
    };

    const int warp = tid >> 5;
    const int lane = tid & 31;
    const int rg  = warp & 3;         // 32-row group
    const int wnq = warp >> 2;        // 0/1
    const int g   = lane >> 2;
    const int tg  = lane & 3;

    float cg[2][4][4], cu[2][4][4];
#pragma unroll
    for (int mi = 0; mi < 2; ++mi)
#pragma unroll
        for (int ni = 0; ni < 4; ++ni)
#pragma unroll
            for (int j = 0; j < 4; ++j) { cg[mi][ni][j] = 0.f; cu[mi][ni][j] = 0.f; }

    load_stage(0, 0); cp_commit();
    load_stage(1, 1); cp_commit();

    const int KS = DD / BK;  // 64
    for (int ks = 0; ks < KS; ++ks) {
        if (ks + 1 < KS) cp_wait1(); else cp_wait0();
        __syncthreads();
        if (ks + 2 < KS) { load_stage(ks + 2, (ks + 2) % NSTG); cp_commit(); }

        const int cur = ks % NSTG;
        const uint4* Aq  = (const uint4*)(As  + cur * 4096);
        const uint4* B1q = (const uint4*)(B1s + cur * 2048);
        const uint4* B2q = (const uint4*)(B2s + cur * 2048);

#pragma unroll
        for (int k8 = 0; k8 < 4; ++k8) {
            uint32_t a[2][4];
#pragma unroll
            for (int mi = 0; mi < 2; ++mi) {
                uint4 qa = Aq[((rg * 4 + k8) * 2 + mi) * 32 + lane];
                a[mi][0] = qa.x; a[mi][1] = qa.y; a[mi][2] = qa.z; a[mi][3] = qa.w;
            }
            const int qb = k8 * 128 + wnq * 64 + lane;
            uint4 q10 = B1q[qb], q11 = B1q[qb + 32];
            uint4 q30 = B2q[qb], q31 = B2q[qb + 32];
            uint32_t b1[4][2], b2[4][2];
            b1[0][0] = q10.x; b1[0][1] = q10.y; b1[1][0] = q10.z; b1[1][1] = q10.w;
            b1[2][0] = q11.x; b1[2][1] = q11.y; b1[3][0] = q11.z; b1[3][1] = q11.w;
            b2[0][0] = q30.x; b2[0][1] = q30.y; b2[1][0] = q30.z; b2[1][1] = q30.w;
            b2[2][0] = q31.x; b2[2][1] = q31.y; b2[3][0] = q31.z; b2[3][1] = q31.w;
#pragma unroll
            for (int mi = 0; mi < 2; ++mi)
#pragma unroll
                for (int ni = 0; ni < 4; ++ni) {
                    mma_tf32(cg[mi][ni], a[mi], b1[ni]);
                    mma_tf32(cu[mi][ni], a[mi], b2[ni]);
                }
        }
    }

    // epilogue: silu(g)*u -> fragment-major g_hf (tf32-rounded)
    const int hb32  = hbase >> 5;
    const int mrem  = cnt - mtile * BM;
    const int wm    = rg * 32;
    const int nbase = ntile * BN + wnq * 32;
#pragma unroll
    for (int mi = 0; mi < 2; ++mi) {
#pragma unroll
        for (int ni = 0; ni < 4; ++ni) {
#pragma unroll
            for (int j = 0; j < 4; ++j) {
                int jh = j >> 1, jl = j & 1;
                int rl = wm + mi * 16 + g + 8 * jh;
                if (rl < mrem) {
                    int c0 = nbase + ni * 8 + tg * 2 + jl;
                    int rgG = hb32 + (rl >> 5);
                    int k8 = c0 >> 3;
                    int lane_d = g * 4 + (c0 & 3);
                    int elem = jh + 2 * ((c0 >> 2) & 1);
                    float gv = cg[mi][ni][j];
                    float uv = cu[mi][ni][j];
                    float s  = gv / (1.0f + __expf(-gv));
                    size_t off = (((size_t)rgG * K8_DN + k8) * 2 + mi) * 128 + lane_d * 4 + elem;
                    g_hf[off] = __uint_as_float(f2tf32(s * uv));
                }
            }
        }
    }
}

// ---------------- kernel: down projection -------------
// grid (mtile, ntile, e), 256 threads, 3 CTAs/SM
__global__ void __launch_bounds__(256, 3)
moe_down_kernel(float* __restrict__ y) {
    const int e     = blockIdx.z;
    const int mtile = blockIdx.x;
    const int ntile = blockIdx.y;
    const int cnt   = g_cnt[e];
    if (mtile * BM >= cnt) return;

    extern __shared__ float sm[];
    float* As = sm;                      // NSTG * 4096 (fragment-major A)
    float* Bs = sm + NSTG * 4096;        // NSTG * 2048
    __shared__ int   stok[BM];
    __shared__ float swt[BM];

    const int tid = threadIdx.x;
    if (tid < BM) {
        int idx = mtile * BM + tid;
        int ok = idx < cnt;
        stok[tid] = ok ? g_tok[e * TT + idx] : 0;
        swt[tid]  = ok ? g_wt[e * TT + idx] : 0.f;
    }
    __syncthreads();

    const int hbase = g_off[e] + mtile * BM;
    const int rg0   = hbase >> 5;
    const float* W2e = g_w2f + ((size_t)(e * NT_DN + ntile) * K8_DN) * 512;

    auto load_stage = [&](int ks, int buf) {
        float* Ab = As + buf * 4096;
#pragma unroll
        for (int v = tid; v < 1024; v += 256) {
            int block = v >> 6, rem = v & 63;
            int rg = block >> 2, k8l = block & 3;
            const float* src = g_hf +
                (((size_t)(rg0 + rg) * K8_DN + ks * 4 + k8l) * 2) * 128 + rem * 4;
            cp_async16(Ab + v * 4, src);
        }
        float* Bb = Bs + buf * 2048;
        const float* s2 = W2e + (size_t)(ks * 4) * 512;
#pragma unroll
        for (int v = tid; v < 512; v += 256) {
            cp_async16(Bb + v * 4, s2 + v * 4);
        }
    };

    const int warp = tid >> 5;
    const int lane = tid & 31;
    const int rg  = warp & 3;
    const int wnq = warp >> 2;
    const int g   = lane >> 2;
    const int tg  = lane & 3;

    float c[2][4][4];
#pragma unroll
    for (int mi = 0; mi < 2; ++mi)
#pragma unroll
        for (int ni = 0; ni < 4; ++ni)
#pragma unroll
            for (int j = 0; j < 4; ++j) c[mi][ni][j] = 0.f;

    load_stage(0, 0); cp_commit();
    load_stage(1, 1); cp_commit();

    const int KS = FF / BK;  // 128
    for (int ks = 0; ks < KS; ++ks) {
        if (ks + 1 < KS) cp_wait1(); else cp_wait0();
        __syncthreads();
        if (ks + 2 < KS) { load_stage(ks + 2, (ks + 2) % NSTG); cp_commit(); }

        const int cur = ks % NSTG;
        const uint4* Aq = (const uint4*)(As + cur * 4096);
        const uint4* Bq = (const uint4*)(Bs + cur * 2048);

#pragma unroll
        for (int k8 = 0; k8 < 4; ++k8) {
            uint32_t a[2][4];
#pragma unroll
            for (int mi = 0; mi < 2; ++mi) {
                uint4 qa = Aq[((rg * 4 + k8) * 2 + mi) * 32 + lane];
                a[mi][0] = qa.x; a[mi][1] = qa.y; a[mi][2] = qa.z; a[mi][3] = qa.w;
            }
            const int qb = k8 * 128 + wnq * 64 + lane;
            uint4 q0 = Bq[qb], q1 = Bq[qb + 32];
            uint32_t b[4][2];
            b[0][0] = q0.x; b[0][1] = q0.y; b[1][0] = q0.z; b[1][1] = q0.w;
            b[2][0] = q1.x; b[2][1] = q1.y; b[3][0] = q1.z; b[3][1] = q1.w;
#pragma unroll
            for (int mi = 0; mi < 2; ++mi)
#pragma unroll
                for (int ni = 0; ni < 4; ++ni)
                    mma_tf32(c[mi][ni], a[mi], b[ni]);
        }
    }

    // epilogue: weighted atomic scatter-add into y
    const int mrem = cnt - mtile * BM;
    const int wm = rg * 32;
    const int wn = wnq * 32;
#pragma unroll
    for (int mi = 0; mi < 2; ++mi) {
#pragma unroll
        for (int ni = 0; ni < 4; ++ni) {
            int r0 = wm + mi * 16 + g;
            int c0 = ntile * BN + wn + ni * 8 + tg * 2;
#pragma unroll
            for (int j = 0; j < 4; ++j) {
                int r = r0 + (j >> 1) * 8;
                int cc = c0 + (j & 1);
                if (r < mrem) {
                    atomicAdd(&y[(size_t)stok[r] * DD + cc], swt[r] * c[mi][ni][j]);
                }
            }
        }
    }
}

// ---------------- launch ------------------------------
extern "C" void kernel_launch(void* const* d_in, const int* in_sizes, int n_in,
                              void* d_out, int out_size) {
    const float* x  = (const float*)d_in[0];
    const float* Wg = (const float*)d_in[1];
    const float* W1 = (const float*)d_in[2];
    const float* W3 = (const float*)d_in[3];
    const float* W2 = (const float*)d_in[4];

    float* y = (float*)d_out;
    float* logits = nullptr;
    int write_logits = 0;
    if ((size_t)out_size >= (size_t)TT * DD + (size_t)TT * EE) {
        logits = y + (size_t)TT * DD;
        write_logits = 1;
    }

    cudaFuncSetAttribute(moe_up_kernel,
                         cudaFuncAttributeMaxDynamicSharedMemorySize, SMEM_UP);
    cudaFuncSetAttribute(moe_down_kernel,
                         cudaFuncAttributeMaxDynamicSharedMemorySize, SMEM_DOWN);

    float *w1f, *w3f, *w2f;
    cudaGetSymbolAddress((void**)&w1f, g_w1f);
    cudaGetSymbolAddress((void**)&w3f, g_w3f);
    cudaGetSymbolAddress((void**)&w2f, g_w2f);

    zero_kernel<<<4096, 256>>>(y, (size_t)TT * DD);
    wfrag_kernel<<<8192, 256>>>(W1, (float4*)w1f, NT_UP, K8_UP, FF);
    wfrag_kernel<<<8192, 256>>>(W3, (float4*)w3f, NT_UP, K8_UP, FF);
    wfrag_kernel<<<8192, 256>>>(W2, (float4*)w2f, NT_DN, K8_DN, DD);

    router_kernel<<<TT / 8, 256>>>(x, Wg, logits, write_logits);
    offsets_kernel<<<1, 32>>>();
    gather_xf_kernel<<<dim3(TT / BM, EE), 256>>>(x);
    moe_up_kernel<<<dim3(TT / BM, NT_UP, EE), 256, SMEM_UP>>>();
    moe_down_kernel<<<dim3(TT / BM, NT_DN, EE), 256, SMEM_DOWN>>>(y);
}